// round 12
// baseline (speedup 1.0000x reference)
#include <cuda_runtime.h>

#define BATCH   128
#define NANCH   8732
#define NCLS    21
#define NLOG    25
#define MAXOUT  5
#define CONF    0.5f
#define NMS_T   256
#define CSTRIDE 32
#define SCAP    448
#define RCAP    2048

#define WPB     4                          // warps per decode block
#define DECBLK  2184                       // decode grid (8736 warps, ~4 tiles each)
#define NWT     (BATCH * NANCH / 32)       // 34928 warp-tiles (exact)
#define TILE_F4 200                        // float4 per warp-tile (32*25/4)

typedef unsigned int       u32;
typedef unsigned long long u64;

__device__ int    g_cnt[BATCH * CSTRIDE];
__device__ float4 g_cbox[BATCH * NANCH];
__device__ u64    g_ckey[BATCH * NANCH];
__device__ float  g_ccls[BATCH * NANCH];

__device__ __forceinline__ void cp16(u32 s, const void* g) {
    asm volatile("cp.async.cg.shared.global [%0], [%1], 16;" :: "r"(s), "l"(g));
}
__device__ __forceinline__ void cp_commit() {
    asm volatile("cp.async.commit_group;");
}
template <int N>
__device__ __forceinline__ void cp_wait() {
    asm volatile("cp.async.wait_group %0;" :: "n"(N));
}

// ---------------------------------------------------------------------------
// Decode: per-warp double-buffered cp.async pipeline. No block barriers.
// Each warp-tile = 32 anchors = 3200 B; lane processes its own anchor from
// its warp's smem chunk (stride-25 floats -> conflict-free, gcd(25,32)=1).
// ---------------------------------------------------------------------------
__global__ void __launch_bounds__(WPB * 32)
decode_kernel(const float* __restrict__ logits, const float* __restrict__ db) {
    __shared__ __align__(16) float buf[WPB][2][TILE_F4 * 4];   // 25.6 KB

    int w    = threadIdx.x >> 5;
    int lane = threadIdx.x & 31;
    int gw   = blockIdx.x * WPB + w;
    int W    = DECBLK * WPB;

    u32 sb0 = (u32)__cvta_generic_to_shared(buf[w][0]);
    u32 sb1 = (u32)__cvta_generic_to_shared(buf[w][1]);

    // prologue: prefetch first tile into buffer 0
    if (gw < NWT) {
        const float4* src = (const float4*)logits + (size_t)gw * TILE_F4;
#pragma unroll
        for (int k = 0; k < 7; k++) {
            int i = lane + 32 * k;
            if (i < TILE_F4) cp16(sb0 + i * 16, src + i);
        }
    }
    cp_commit();

    int s = 0;
    for (int t = gw; t < NWT; t += W, s ^= 1) {
        int nx = t + W;
        if (nx < NWT) {
            const float4* src = (const float4*)logits + (size_t)nx * TILE_F4;
            u32 sb = s ? sb0 : sb1;
#pragma unroll
            for (int k = 0; k < 7; k++) {
                int i = lane + 32 * k;
                if (i < TILE_F4) cp16(sb + i * 16, src + i);
            }
            cp_commit();
            cp_wait<1>();                  // current tile resident
        } else {
            cp_wait<0>();
        }
        __syncwarp();                      // cross-lane smem visibility

        const float* L = buf[w][s] + lane * NLOG;
        int a = t * 32 + lane;             // global anchor id

        float c0 = L[4];                   // background logit
        float m1 = L[5];                   // max over classes 1..20
#pragma unroll
        for (int c = 2; c < NCLS; c++) m1 = fmaxf(m1, L[4 + c]);
        float mx = fmaxf(c0, m1);

        float sum = 0.f;
#pragma unroll
        for (int c = 0; c < NCLS; c++) sum += __expf(L[4 + c] - mx);
        float score = 1.0f / sum;

        if (m1 > c0 && score > CONF) {     // argmax != 0 && score > 0.5
            int bi = 1;                    // first-occurrence class among 1..20
#pragma unroll
            for (int c = NCLS - 1; c >= 1; c--) if (L[4 + c] == m1) bi = c;

            int b = a / NANCH;
            int n = a % NANCH;
            float4 d = ((const float4*)db)[n];
            float cy = 0.5f * (d.z + d.x);
            float cx = 0.5f * (d.w + d.y);
            float h  = d.z - d.x;
            float ww = d.w - d.y;
            float ncy = L[0] * h + cy;
            float ncx = L[1] * ww + cx;
            float nh  = __expf(L[2]) * h;
            float nw  = __expf(L[3]) * ww;
            float4 box;
            box.x = fminf(fmaxf(ncy - 0.5f * nh, 0.f), 1.f);
            box.y = fminf(fmaxf(ncx - 0.5f * nw, 0.f), 1.f);
            box.z = fminf(fmaxf(ncy + 0.5f * nh, 0.f), 1.f);
            box.w = fminf(fmaxf(ncx + 0.5f * nw, 0.f), 1.f);

            int slot = atomicAdd(&g_cnt[b * CSTRIDE], 1);
            size_t o = (size_t)b * NANCH + slot;
            u32 hi = __float_as_uint(score) | 0x80000000u;
            u32 lo = ((u32)(NANCH - n) << 14) | (u32)slot;
            g_ckey[o] = ((u64)hi << 32) | lo;
            g_cbox[o] = box;
            g_ccls[o] = (float)bi;
        }
        __syncwarp();                      // reads done before buffer reuse
    }
    cudaTriggerProgrammaticLaunchCompletion();
}

// ---------------------------------------------------------------------------
// NMS (R11): stage to smem, warp 0 runs no-store bitmask suppress+argmax.
// ---------------------------------------------------------------------------
__global__ void __launch_bounds__(NMS_T)
nms_kernel(float* __restrict__ out) {
    __shared__ u64    skey[SCAP];
    __shared__ float4 sbox[SCAP];

    cudaGridDependencySynchronize();

    int b   = blockIdx.x;
    int tid = threadIdx.x;
    int M   = g_cnt[b * CSTRIDE];
    size_t base = (size_t)b * NANCH;

    bool fits = (M <= SCAP);
    if (fits) {
        for (int i = tid; i < M; i += NMS_T) {
            skey[i] = g_ckey[base + i];
            sbox[i] = g_cbox[base + i];
        }
    }
    __syncthreads();
    if (tid == 0) g_cnt[b * CSTRIDE] = 0;

    if (tid >= 32) return;
    float* ob = out + (size_t)b * MAXOUT * 6;

    if (M <= RCAP) {
        const u64*    __restrict__ keys  = fits ? skey : (g_ckey + base);
        const float4* __restrict__ boxes = fits ? sbox : (g_cbox + base);
        u64 alive = ~0ull;
        u64 bp = 0ull;
        for (int i = tid; i < M; i += 32) {
            u64 k = keys[i];
            if (k > bp) bp = k;
        }
#pragma unroll
        for (int off = 16; off > 0; off >>= 1) {
            u64 o = __shfl_xor_sync(0xffffffffu, bp, off);
            if (o > bp) bp = o;
        }
        for (int t = 0; t < MAXOUT; t++) {
            if (bp == 0ull) {
                if (tid == 0)
                    for (int tt = t; tt < MAXOUT; tt++) {
                        float* o = ob + tt * 6;
                        o[0]=o[1]=o[2]=o[3]=o[4]=o[5]=0.f;
                    }
                return;
            }
            int   pos = (int)(bp & 0x3FFFull);
            float sc  = __uint_as_float((u32)(bp >> 32) & 0x7FFFFFFFu);
            float4 B  = boxes[pos];
            if (tid == 0) {
                float* o = ob + t * 6;
                o[0]=B.x; o[1]=B.y; o[2]=B.z; o[3]=B.w;
                o[4]=g_ccls[base + pos]; o[5]=sc;
            }
            if (t == MAXOUT - 1) return;

            float a1 = (B.z - B.x) * (B.w - B.y);
            bp = 0ull;
            int kk = 0;
            for (int i = tid; i < M; i += 32, kk++) {
                if (!((alive >> kk) & 1ull)) continue;
                float4 C = boxes[i];
                float ty  = fmaxf(B.x, C.x);
                float tx  = fmaxf(B.y, C.y);
                float by  = fminf(B.z, C.z);
                float bxr = fminf(B.w, C.w);
                float hh  = fmaxf(by - ty, 0.f);
                float ww  = fmaxf(bxr - tx, 0.f);
                float inter = hh * ww;
                float a2 = (C.z - C.x) * (C.w - C.y);
                float iou = inter / (a1 + a2 - inter + 1e-12f);
                if (iou > 0.5f) alive &= ~(1ull << kk);
                else {
                    u64 k = keys[i];
                    if (k > bp) bp = k;
                }
            }
#pragma unroll
            for (int off = 16; off > 0; off >>= 1) {
                u64 o = __shfl_xor_sync(0xffffffffu, bp, off);
                if (o > bp) bp = o;
            }
        }
    } else {
        // destructive fallback (never expected at these sizes)
        u64* kg = g_ckey + base;
        const float4* boxes = g_cbox + base;
        u64 bp = 0ull;
        for (int i = tid; i < M; i += 32) {
            u64 k = kg[i];
            if (k > bp) bp = k;
        }
#pragma unroll
        for (int off = 16; off > 0; off >>= 1) {
            u64 o = __shfl_xor_sync(0xffffffffu, bp, off);
            if (o > bp) bp = o;
        }
        for (int t = 0; t < MAXOUT; t++) {
            if (bp == 0ull) {
                if (tid == 0)
                    for (int tt = t; tt < MAXOUT; tt++) {
                        float* o = ob + tt * 6;
                        o[0]=o[1]=o[2]=o[3]=o[4]=o[5]=0.f;
                    }
                return;
            }
            int   pos = (int)(bp & 0x3FFFull);
            float sc  = __uint_as_float((u32)(bp >> 32) & 0x7FFFFFFFu);
            float4 B  = boxes[pos];
            if (tid == 0) {
                float* o = ob + t * 6;
                o[0]=B.x; o[1]=B.y; o[2]=B.z; o[3]=B.w;
                o[4]=g_ccls[base + pos]; o[5]=sc;
            }
            if (t == MAXOUT - 1) return;
            float a1 = (B.z - B.x) * (B.w - B.y);
            bp = 0ull;
            for (int i = tid; i < M; i += 32) {
                u64 k = kg[i];
                if (!k) continue;
                float4 C = boxes[i];
                float ty  = fmaxf(B.x, C.x);
                float tx  = fmaxf(B.y, C.y);
                float by  = fminf(B.z, C.z);
                float bxr = fminf(B.w, C.w);
                float hh  = fmaxf(by - ty, 0.f);
                float ww  = fmaxf(bxr - tx, 0.f);
                float inter = hh * ww;
                float a2 = (C.z - C.x) * (C.w - C.y);
                float iou = inter / (a1 + a2 - inter + 1e-12f);
                if (iou > 0.5f) kg[i] = 0ull;
                else if (k > bp) bp = k;
            }
#pragma unroll
            for (int off = 16; off > 0; off >>= 1) {
                u64 o = __shfl_xor_sync(0xffffffffu, bp, off);
                if (o > bp) bp = o;
            }
        }
    }
}

// ---------------------------------------------------------------------------
extern "C" void kernel_launch(void* const* d_in, const int* in_sizes, int n_in,
                              void* d_out, int out_size) {
    const float* logits = (const float*)d_in[0];   // [128, 8732, 25]
    const float* db     = (const float*)d_in[1];   // [8732, 4]
    float*       out    = (float*)d_out;           // [128, 5, 6]

    decode_kernel<<<DECBLK, WPB * 32>>>(logits, db);

    cudaLaunchConfig_t cfg = {};
    cfg.gridDim  = dim3(BATCH);
    cfg.blockDim = dim3(NMS_T);
    cfg.dynamicSmemBytes = 0;
    cfg.stream = 0;
    cudaLaunchAttribute attr[1];
    attr[0].id = cudaLaunchAttributeProgrammaticStreamSerialization;
    attr[0].val.programmaticStreamSerializationAllowed = 1;
    cfg.attrs = attr;
    cfg.numAttrs = 1;
    cudaLaunchKernelEx(&cfg, nms_kernel, out);
}

// round 13
// speedup vs baseline: 1.0077x; 1.0077x over previous
#include <cuda_runtime.h>

#define BATCH   128
#define NANCH   8732
#define NCLS    21
#define NLOG    25
#define MAXOUT  5
#define CONF    0.5f
#define DEC_T   128
#define NMS_T   256
#define CSTRIDE 32
#define SCAP    448
#define RCAP    2048

typedef unsigned int       u32;
typedef unsigned long long u64;

__device__ int    g_cnt[BATCH * CSTRIDE];
__device__ float4 g_cbox[BATCH * NANCH];
__device__ u64    g_ckey[BATCH * NANCH];
__device__ float  g_ccls[BATCH * NANCH];

__device__ __forceinline__ void cp16(u32 s, const void* g) {
    asm volatile("cp.async.cg.shared.global [%0], [%1], 16;" :: "r"(s), "l"(g));
}
__device__ __forceinline__ void cp_commit() {
    asm volatile("cp.async.commit_group;");
}
template <int N>
__device__ __forceinline__ void cp_wait() {
    asm volatile("cp.async.wait_group %0;" :: "n"(N));
}

// ---------------------------------------------------------------------------
// Decode: cp.async staging (zero register cost -> 16 blocks/SM) + lazy argmax.
// ---------------------------------------------------------------------------
__global__ void __launch_bounds__(DEC_T, 16)
decode_kernel(const float* __restrict__ logits, const float* __restrict__ db) {
    __shared__ __align__(16) float tile[DEC_T * NLOG];     // 12.8 KB
    const int NV = DEC_T * NLOG / 4;                       // 800 float4

    int tid = threadIdx.x;
    long long base = (long long)blockIdx.x * DEC_T;
    const float4* __restrict__ src = (const float4*)(logits + base * NLOG);

    u32 sb = (u32)__cvta_generic_to_shared(tile);
#pragma unroll
    for (int k = 0; k < 7; k++) {
        int i = tid + k * DEC_T;
        if (i < NV) cp16(sb + i * 16, src + i);
    }
    cp_commit();
    cp_wait<0>();
    __syncthreads();

    int gid = (int)base + tid;
    const float* L = tile + tid * NLOG;

    float c0 = L[4];                       // background logit
    float m1 = L[5];                       // max over classes 1..20
#pragma unroll
    for (int c = 2; c < NCLS; c++) m1 = fmaxf(m1, L[4 + c]);
    float mx = fmaxf(c0, m1);

    float sum = 0.f;
#pragma unroll
    for (int c = 0; c < NCLS; c++) sum += __expf(L[4 + c] - mx);
    float score = 1.0f / sum;

    if (m1 > c0 && score > CONF) {         // argmax != 0 && score > 0.5
        int bi = 1;                        // first-occurrence class among 1..20
#pragma unroll
        for (int c = NCLS - 1; c >= 1; c--) if (L[4 + c] == m1) bi = c;

        int b = gid / NANCH;
        int n = gid % NANCH;
        float4 d = ((const float4*)db)[n];                 // y0,x0,y1,x1
        float cy = 0.5f * (d.z + d.x);
        float cx = 0.5f * (d.w + d.y);
        float h  = d.z - d.x;
        float w  = d.w - d.y;
        float ncy = L[0] * h + cy;
        float ncx = L[1] * w + cx;
        float nh  = __expf(L[2]) * h;
        float nw  = __expf(L[3]) * w;
        float4 box;
        box.x = fminf(fmaxf(ncy - 0.5f * nh, 0.f), 1.f);
        box.y = fminf(fmaxf(ncx - 0.5f * nw, 0.f), 1.f);
        box.z = fminf(fmaxf(ncy + 0.5f * nh, 0.f), 1.f);
        box.w = fminf(fmaxf(ncx + 0.5f * nw, 0.f), 1.f);

        int slot = atomicAdd(&g_cnt[b * CSTRIDE], 1);
        size_t o = (size_t)b * NANCH + slot;
        u32 hi = __float_as_uint(score) | 0x80000000u;
        u32 lo = ((u32)(NANCH - n) << 14) | (u32)slot;
        g_ckey[o] = ((u64)hi << 32) | lo;
        g_cbox[o] = box;
        g_ccls[o] = (float)bi;
    }
    cudaTriggerProgrammaticLaunchCompletion();
}

// ---------------------------------------------------------------------------
// NMS (R11-proven): stage to smem, warp 0 runs no-store bitmask suppress+argmax.
// ---------------------------------------------------------------------------
__global__ void __launch_bounds__(NMS_T)
nms_kernel(float* __restrict__ out) {
    __shared__ u64    skey[SCAP];
    __shared__ float4 sbox[SCAP];

    cudaGridDependencySynchronize();

    int b   = blockIdx.x;
    int tid = threadIdx.x;
    int M   = g_cnt[b * CSTRIDE];
    size_t base = (size_t)b * NANCH;

    bool fits = (M <= SCAP);
    if (fits) {
        for (int i = tid; i < M; i += NMS_T) {
            skey[i] = g_ckey[base + i];
            sbox[i] = g_cbox[base + i];
        }
    }
    __syncthreads();
    if (tid == 0) g_cnt[b * CSTRIDE] = 0;

    if (tid >= 32) return;
    float* ob = out + (size_t)b * MAXOUT * 6;

    if (M <= RCAP) {
        const u64*    __restrict__ keys  = fits ? skey : (g_ckey + base);
        const float4* __restrict__ boxes = fits ? sbox : (g_cbox + base);
        u64 alive = ~0ull;
        u64 bp = 0ull;
        for (int i = tid; i < M; i += 32) {
            u64 k = keys[i];
            if (k > bp) bp = k;
        }
#pragma unroll
        for (int off = 16; off > 0; off >>= 1) {
            u64 o = __shfl_xor_sync(0xffffffffu, bp, off);
            if (o > bp) bp = o;
        }
        for (int t = 0; t < MAXOUT; t++) {
            if (bp == 0ull) {
                if (tid == 0)
                    for (int tt = t; tt < MAXOUT; tt++) {
                        float* o = ob + tt * 6;
                        o[0]=o[1]=o[2]=o[3]=o[4]=o[5]=0.f;
                    }
                return;
            }
            int   pos = (int)(bp & 0x3FFFull);
            float sc  = __uint_as_float((u32)(bp >> 32) & 0x7FFFFFFFu);
            float4 B  = boxes[pos];
            if (tid == 0) {
                float* o = ob + t * 6;
                o[0]=B.x; o[1]=B.y; o[2]=B.z; o[3]=B.w;
                o[4]=g_ccls[base + pos]; o[5]=sc;
            }
            if (t == MAXOUT - 1) return;

            float a1 = (B.z - B.x) * (B.w - B.y);
            bp = 0ull;
            int kk = 0;
            for (int i = tid; i < M; i += 32, kk++) {
                if (!((alive >> kk) & 1ull)) continue;
                float4 C = boxes[i];
                float ty  = fmaxf(B.x, C.x);
                float tx  = fmaxf(B.y, C.y);
                float by  = fminf(B.z, C.z);
                float bxr = fminf(B.w, C.w);
                float hh  = fmaxf(by - ty, 0.f);
                float ww  = fmaxf(bxr - tx, 0.f);
                float inter = hh * ww;
                float a2 = (C.z - C.x) * (C.w - C.y);
                float iou = inter / (a1 + a2 - inter + 1e-12f);
                if (iou > 0.5f) alive &= ~(1ull << kk);
                else {
                    u64 k = keys[i];
                    if (k > bp) bp = k;
                }
            }
#pragma unroll
            for (int off = 16; off > 0; off >>= 1) {
                u64 o = __shfl_xor_sync(0xffffffffu, bp, off);
                if (o > bp) bp = o;
            }
        }
    } else {
        // destructive fallback (never expected at these sizes)
        u64* kg = g_ckey + base;
        const float4* boxes = g_cbox + base;
        u64 bp = 0ull;
        for (int i = tid; i < M; i += 32) {
            u64 k = kg[i];
            if (k > bp) bp = k;
        }
#pragma unroll
        for (int off = 16; off > 0; off >>= 1) {
            u64 o = __shfl_xor_sync(0xffffffffu, bp, off);
            if (o > bp) bp = o;
        }
        for (int t = 0; t < MAXOUT; t++) {
            if (bp == 0ull) {
                if (tid == 0)
                    for (int tt = t; tt < MAXOUT; tt++) {
                        float* o = ob + tt * 6;
                        o[0]=o[1]=o[2]=o[3]=o[4]=o[5]=0.f;
                    }
                return;
            }
            int   pos = (int)(bp & 0x3FFFull);
            float sc  = __uint_as_float((u32)(bp >> 32) & 0x7FFFFFFFu);
            float4 B  = boxes[pos];
            if (tid == 0) {
                float* o = ob + t * 6;
                o[0]=B.x; o[1]=B.y; o[2]=B.z; o[3]=B.w;
                o[4]=g_ccls[base + pos]; o[5]=sc;
            }
            if (t == MAXOUT - 1) return;
            float a1 = (B.z - B.x) * (B.w - B.y);
            bp = 0ull;
            for (int i = tid; i < M; i += 32) {
                u64 k = kg[i];
                if (!k) continue;
                float4 C = boxes[i];
                float ty  = fmaxf(B.x, C.x);
                float tx  = fmaxf(B.y, C.y);
                float by  = fminf(B.z, C.z);
                float bxr = fminf(B.w, C.w);
                float hh  = fmaxf(by - ty, 0.f);
                float ww  = fmaxf(bxr - tx, 0.f);
                float inter = hh * ww;
                float a2 = (C.z - C.x) * (C.w - C.y);
                float iou = inter / (a1 + a2 - inter + 1e-12f);
                if (iou > 0.5f) kg[i] = 0ull;
                else if (k > bp) bp = k;
            }
#pragma unroll
            for (int off = 16; off > 0; off >>= 1) {
                u64 o = __shfl_xor_sync(0xffffffffu, bp, off);
                if (o > bp) bp = o;
            }
        }
    }
}

// ---------------------------------------------------------------------------
extern "C" void kernel_launch(void* const* d_in, const int* in_sizes, int n_in,
                              void* d_out, int out_size) {
    const float* logits = (const float*)d_in[0];   // [128, 8732, 25]
    const float* db     = (const float*)d_in[1];   // [8732, 4]
    float*       out    = (float*)d_out;           // [128, 5, 6]

    decode_kernel<<<BATCH * NANCH / DEC_T, DEC_T>>>(logits, db);

    cudaLaunchConfig_t cfg = {};
    cfg.gridDim  = dim3(BATCH);
    cfg.blockDim = dim3(NMS_T);
    cfg.dynamicSmemBytes = 0;
    cfg.stream = 0;
    cudaLaunchAttribute attr[1];
    attr[0].id = cudaLaunchAttributeProgrammaticStreamSerialization;
    attr[0].val.programmaticStreamSerializationAllowed = 1;
    cfg.attrs = attr;
    cfg.numAttrs = 1;
    cudaLaunchKernelEx(&cfg, nms_kernel, out);
}